// round 13
// baseline (speedup 1.0000x reference)
#include <cuda_runtime.h>

#define Wd 192
#define Hd 192
#define HW (Wd * Hd)
#define Hm 190
#define Wm 190
#define NBG 32     // B*G = 2*16
#define SPLIT 10
#define RS 19      // rows per strip (190/10)
#define TROWS (RS + 2)          // tile rows per plane (19 + 2 border)
#define PLSTRIDE (TROWS * Wd)   // floats per plane tile

// Kernel C tiling
#define CROWS 16                    // output rows per block
#define CSROWS (CROWS + 4)          // staged rows (halo 2 each side)
#define CPL (CSROWS * Wd)           // floats per staged plane (3840)

#define FLOOR_MAGIC 12582912.0f     // 1.5 * 2^23

// Scratch (device globals; no runtime allocation)
__device__ double g_part[288 * SPLIT * 36];  // partial triangular grams
__device__ int    g_nnA[NBG * 9];
__device__ int    g_nnK[NBG * 9];
__device__ float  g_cnt[NBG * 9];

// ---------------------------------------------------------------------------
// Kernel A: per (bg, j, strip) partial 8x8 gram of motif rows.
// Motif row c -> flat F=8j+c -> (a=F/9, k=F%9); value = feat[a, k/3+y, k%3+x].
// 8 rows span <=2 adjacent planes -> smem tiles; J compile-time -> LDS imm.
// ---------------------------------------------------------------------------
template<int J>
__device__ __forceinline__ void gram_body(const float* __restrict__ fb,
                                          const int strip, const int blk,
                                          float* __restrict__ tile,
                                          float (*part)[36]) {
    constexpr int A_LO = (8 * J) / 9;
    constexpr int A_HI = (8 * J + 7) / 9;
    constexpr int NPL  = (A_HI == A_LO) ? 1 : 2;
    constexpr int V4_PER_PL = TROWS * (Wd / 4);

    const int y0 = strip * RS;
    {
        float4* t4 = (float4*)tile;
        for (int i = threadIdx.x; i < NPL * V4_PER_PL; i += 192) {
            const int pl  = i / V4_PER_PL;
            const int rem = i - pl * V4_PER_PL;
            const int rr  = rem / (Wd / 4);
            const int c4  = rem - rr * (Wd / 4);
            const float4* src =
                (const float4*)(fb + (size_t)(A_LO + pl) * HW + (y0 + rr) * Wd) + c4;
            t4[i] = *src;
        }
    }
    __syncthreads();

    float acc[36];
#pragma unroll
    for (int t = 0; t < 36; t++) acc[t] = 0.f;

    const int x = threadIdx.x;
    if (x < Wm) {
        int base = x;
#pragma unroll 2
        for (int r = 0; r < RS; r++) {
            float m[8];
#pragma unroll
            for (int c = 0; c < 8; c++) {
                const int F = 8 * J + c;          // compile-time
                const int a = F / 9, k = F % 9;   // compile-time
                m[c] = tile[(a - A_LO) * PLSTRIDE + (k / 3) * Wd + (k % 3) + base];
            }
            int t = 0;
#pragma unroll
            for (int c = 0; c < 8; c++)
#pragma unroll
                for (int d = c; d < 8; d++) {
                    acc[t] += m[c] * m[d];
                    t++;
                }
            base += Wd;
        }
    }

    const int lane = threadIdx.x & 31, wid = threadIdx.x >> 5;
#pragma unroll
    for (int t = 0; t < 36; t++) {
#pragma unroll
        for (int sh = 16; sh > 0; sh >>= 1)
            acc[t] += __shfl_down_sync(0xffffffffu, acc[t], sh);
    }
    if (lane == 0) {
#pragma unroll
        for (int t = 0; t < 36; t++) part[wid][t] = acc[t];
    }
    __syncthreads();

    if (threadIdx.x < 36) {
        double s = 0.0;
#pragma unroll
        for (int w6 = 0; w6 < 6; w6++) s += (double)part[w6][threadIdx.x];
        g_part[((size_t)blk * SPLIT + strip) * 36 + threadIdx.x] = s;
    }
}

__global__ __launch_bounds__(192) void motif_gram_kernel(const float* __restrict__ f) {
    const int blk   = blockIdx.x;     // 0..287 = bg*9 + j
    const int strip = blockIdx.y;     // 0..9
    const int bg    = blk / 9;
    const int j     = blk % 9;
    const float* fb = f + (size_t)bg * 8 * HW;

    __shared__ __align__(16) float tile[2 * PLSTRIDE];   // 32256 B
    __shared__ float part[6][36];

    switch (j) {   // block-uniform branch
        case 0: gram_body<0>(fb, strip, blk, tile, part); break;
        case 1: gram_body<1>(fb, strip, blk, tile, part); break;
        case 2: gram_body<2>(fb, strip, blk, tile, part); break;
        case 3: gram_body<3>(fb, strip, blk, tile, part); break;
        case 4: gram_body<4>(fb, strip, blk, tile, part); break;
        case 5: gram_body<5>(fb, strip, blk, tile, part); break;
        case 6: gram_body<6>(fb, strip, blk, tile, part); break;
        case 7: gram_body<7>(fb, strip, blk, tile, part); break;
        default: gram_body<8>(fb, strip, blk, tile, part); break;
    }
}

// ---------------------------------------------------------------------------
// Kernel B: reduce strip partials -> grams; argmin (diag excluded, first-min
// tie-break); per j: u = max nn, cnt = #{nn==u}.
// ---------------------------------------------------------------------------
__global__ __launch_bounds__(128) void motif_argmin_kernel() {
    const int bg = blockIdx.x;
    const int t  = threadIdx.x;
    __shared__ double G[9 * 64];
    __shared__ int nn[72];

    for (int e = t; e < 9 * 36; e += 128) {
        const int j = e / 36;
        int rem = e % 36, c = 0;
        while (rem >= 8 - c) { rem -= (8 - c); c++; }
        const int d = c + rem;
        double sum = 0.0;
#pragma unroll
        for (int sl = 0; sl < SPLIT; sl++)
            sum += g_part[((size_t)(bg * 9 + j) * SPLIT + sl) * 36 + (e % 36)];
        G[j * 64 + c * 8 + d] = sum;
        G[j * 64 + d * 8 + c] = sum;
    }
    __syncthreads();

    if (t < 72) {
        const int j = t / 8, c = t % 8;
        const double* gj = G + j * 64;
        const double scc = gj[c * 8 + c];
        double best = 1e300;
        int bi = 0;
        for (int d = 0; d < 8; d++) {
            if (d == c) continue;
            const double d2 = scc + gj[d * 8 + d] - 2.0 * gj[c * 8 + d];
            if (d2 < best) { best = d2; bi = d; }
        }
        nn[t] = bi;
    }
    __syncthreads();

    if (t < 9) {
        int u = 0, cnt = 0;
        for (int c = 0; c < 8; c++) u = max(u, nn[t * 8 + c]);
        for (int c = 0; c < 8; c++) cnt += (nn[t * 8 + c] == u) ? 1 : 0;
        const int fn = 8 * t + u;
        g_nnA[bg * 9 + t] = fn / 9;
        g_nnK[bg * 9 + t] = fn % 9;
        g_cnt[bg * 9 + t] = (float)cnt;
    }
}

// ---------------------------------------------------------------------------
// Kernel C: smem-staged gather fold. Block = (plane bc, 16-row tile).
// Since an - cnew in {-1,0,1} (proved for all cnew), stage 3 planes x 20 rows.
// All neighbor reads become conflict-free LDS. floor() via round-down magic
// (exact for |x| < 2^22). out = mask*nv*self + sum_k floor((self*nb)*(cnt/8)).
// ---------------------------------------------------------------------------
__global__ __launch_bounds__(192) void motif_out_kernel(const float* __restrict__ f,
                                                        float* __restrict__ out) {
    const int bc = blockIdx.x;        // b*128 + cglob
    const int b = bc >> 7, cglob = bc & 127;
    const int g = cglob >> 3, cnew = cglob & 7;
    const int bg = b * 16 + g;

    __shared__ __align__(16) float sm[3 * CPL];   // 46080 B
    __shared__ int   s_doff[9];
    __shared__ float s_cs[9];

    if (threadIdx.x < 9) {
        const int knew = threadIdx.x;
        const int j = (cnew * 9 + knew) >> 3;
        const int an = g_nnA[bg * 9 + j];     // an - cnew in {-1,0,1}
        const int kn = g_nnK[bg * 9 + j];
        s_cs[knew] = g_cnt[bg * 9 + j] * 0.125f;   // exact
        const int dh = kn / 3 - knew / 3;
        const int dw = kn % 3 - knew % 3;
        s_doff[knew] = (an - cnew) * CPL + dh * Wd + dw;
    }

    // Stage 3 planes (cnew-1, cnew, cnew+1 clamped to [0,7]) x CSROWS rows.
    const int r0 = blockIdx.y * CROWS;
    const float* fgrp = f + ((size_t)b * 128 + (size_t)g * 8) * HW;
    {
        float4* sm4 = (float4*)sm;
        constexpr int V4_PL = CSROWS * (Wd / 4);   // 960
        for (int i = threadIdx.x; i < 3 * V4_PL; i += 192) {
            const int p   = i / V4_PL;
            const int rem = i - p * V4_PL;
            const int ri  = rem / (Wd / 4);
            const int c4  = rem - ri * (Wd / 4);
            int ch = cnew + p - 1; ch = min(7, max(0, ch));
            int gr = r0 - 2 + ri;  gr = min(Hd - 1, max(0, gr));
            sm4[i] = ((const float4*)(fgrp + (size_t)ch * HW + gr * Wd))[c4];
        }
    }
    __syncthreads();

    int   doff[9];
    float csr[9];
#pragma unroll
    for (int k = 0; k < 9; k++) { doff[k] = s_doff[k]; csr[k] = s_cs[k]; }

    const int w = threadIdx.x;
    const bool wv0 = ((unsigned)w       <= (Wm - 1));
    const bool wv1 = ((unsigned)(w - 1) <= (Wm - 1));
    const bool wv2 = ((unsigned)(w - 2) <= (Wm - 1));
    const bool win = wv0 & wv1 & wv2;
    const float mask = (b != 0) ? 1.0f : 0.0f;
    float* oc = out + (size_t)bc * HW;

#pragma unroll 2
    for (int lr = 0; lr < CROWS; lr++) {
        const int h = r0 + lr;
        const int sb = CPL + (lr + 2) * Wd + w;   // self position in plane 1
        const float self = sm[sb];
        float acc = 0.f;
        float nvf;

        const bool hv0 = ((unsigned)h       <= (Hm - 1));
        const bool hv1 = ((unsigned)(h - 1) <= (Hm - 1));
        const bool hv2 = ((unsigned)(h - 2) <= (Hm - 1));

        if ((hv0 & hv1 & hv2) & win) {          // interior
            nvf = 9.0f;
            float nb[9];
#pragma unroll
            for (int k = 0; k < 9; k++) nb[k] = sm[sb + doff[k]];
#pragma unroll
            for (int k = 0; k < 9; k++) {
                float tv = self * nb[k];        // fl(m*mn)
                tv = tv * csr[k];               // = fl(tv*cnt)*2^-3 exactly
                const float y = __fadd_rd(tv, FLOOR_MAGIC);   // floor(tv)+MAGIC
                acc += (y - FLOOR_MAGIC);
            }
        } else {                                 // boundary: predicated
            const bool hv[3] = {hv0, hv1, hv2};
            const bool wv[3] = {wv0, wv1, wv2};
            const int nv = ((int)hv0 + (int)hv1 + (int)hv2)
                         * ((int)wv0 + (int)wv1 + (int)wv2);
            nvf = (float)nv;
#pragma unroll
            for (int k = 0; k < 9; k++) {
                const bool v = hv[k / 3] & wv[k % 3];
                const int  o = v ? doff[k] : 0;  // self fallback (staged, safe)
                const float nbv = sm[sb + o];
                float tv = self * nbv;
                tv = tv * csr[k];
                const float y = __fadd_rd(tv, FLOOR_MAGIC);
                acc += v ? (y - FLOOR_MAGIC) : 0.0f;
            }
        }
        oc[h * Wd + w] = acc + mask * nvf * self;
    }
}

extern "C" void kernel_launch(void* const* d_in, const int* in_sizes, int n_in,
                              void* d_out, int out_size) {
    const float* f = (const float*)d_in[0];
    float* out = (float*)d_out;
    (void)in_sizes; (void)n_in; (void)out_size;

    motif_gram_kernel<<<dim3(288, SPLIT), 192>>>(f);
    motif_argmin_kernel<<<32, 128>>>();
    motif_out_kernel<<<dim3(256, Hd / CROWS), 192>>>(f, out);
}